// round 16
// baseline (speedup 1.0000x reference)
#include <cuda_runtime.h>
#include <cuda_fp16.h>
#include <mma.h>
#include <cstdint>
#include <math.h>

using namespace nvcuda;

// Problem constants
#define SEQ   4096
#define BATCH 8
#define DIMN  1024
#define TOK   (SEQ * BATCH)                 // 32768 rows

// ---------------- scratch (device globals; no allocation allowed) ----------
__device__ float g_inp [(size_t)TOK * DIMN];
__device__ float g_gate[(size_t)TOK * DIMN];
__device__ float g_u   [(size_t)TOK * DIMN];    // becomes v after ADDC GEMM
__device__ float g_bl  [2 * BATCH * DIMN];      // blended, double-buffered
__device__ unsigned g_flags[128 * 32];          // per-CTA flag, own 128B line

// fp16 hi/lo split operands
__device__ __half g_xhi[(size_t)TOK * DIMN], g_xlo[(size_t)TOK * DIMN];
__device__ __half g_ihi[(size_t)TOK * DIMN], g_ilo[(size_t)TOK * DIMN];
__device__ __half g_whi[(size_t)TOK * DIMN], g_wlo[(size_t)TOK * DIMN];
__device__ __half g_shi[(size_t)TOK * DIMN], g_slo[(size_t)TOK * DIMN];
__device__ __half g_Winh[DIMN * DIMN], g_Winl[DIMN * DIMN];
__device__ __half g_Bh  [DIMN * DIMN], g_Bl  [DIMN * DIMN];
__device__ __half g_Wgh [DIMN * DIMN], g_Wgl [DIMN * DIMN];
__device__ __half g_Ah  [DIMN * DIMN], g_Al  [DIMN * DIMN];
__device__ __half g_Woh [DIMN * DIMN], g_Wol [DIMN * DIMN];

// ---------------- f32x2 helpers --------------------------------------------
__device__ __forceinline__ unsigned long long fma2(unsigned long long a,
                                                   unsigned long long b,
                                                   unsigned long long c) {
    unsigned long long d;
    asm("fma.rn.f32x2 %0, %1, %2, %3;" : "=l"(d) : "l"(a), "l"(b), "l"(c));
    return d;
}
__device__ __forceinline__ float lo32(unsigned long long v) { return __uint_as_float((unsigned)v); }
__device__ __forceinline__ float hi32(unsigned long long v) { return __uint_as_float((unsigned)(v >> 32)); }

// ---------------- distributed-flag barrier primitives ----------------------
__device__ __forceinline__ void st_release_u32(unsigned* p, unsigned v) {
    asm volatile("st.release.gpu.global.u32 [%0], %1;" :: "l"(p), "r"(v) : "memory");
}
__device__ __forceinline__ unsigned ld_acquire_u32(const unsigned* p) {
    unsigned v;
    asm volatile("ld.acquire.gpu.global.u32 %0, [%1];" : "=r"(v) : "l"(p) : "memory");
    return v;
}

// ---------------- fp16 hi/lo split helpers ---------------------------------
__device__ __forceinline__ void split4h(float4 v, __half* hi, __half* lo) {
    __half h0 = __float2half_rn(v.x), h1 = __float2half_rn(v.y);
    __half h2 = __float2half_rn(v.z), h3 = __float2half_rn(v.w);
    __half l0 = __float2half_rn(v.x - __half2float(h0));
    __half l1 = __float2half_rn(v.y - __half2float(h1));
    __half l2 = __float2half_rn(v.z - __half2float(h2));
    __half l3 = __float2half_rn(v.w - __half2float(h3));
    ((__half2*)hi)[0] = __halves2half2(h0, h1);
    ((__half2*)hi)[1] = __halves2half2(h2, h3);
    ((__half2*)lo)[0] = __halves2half2(l0, l1);
    ((__half2*)lo)[1] = __halves2half2(l2, l3);
}

// ---------------- fused prep: all splits + flag reset in ONE launch --------
#define XBLKS  32768                    // TOK*DIMN/4/256
#define WBLKS  1024                     // DIMN*DIMN/4/256
#define PREP_BLKS (XBLKS + 5 * WBLKS + 16)

__global__ void prep_kernel(const float* __restrict__ x,
                            const float* __restrict__ W_in,
                            const float* __restrict__ Bm,
                            const float* __restrict__ W_g,
                            const float* __restrict__ Am,
                            const float* __restrict__ W_out)
{
    const int bid = blockIdx.x;
    const int t   = threadIdx.x;
    if (bid < XBLKS) {
        const size_t i = (size_t)bid * 256 + t;
        float4 v = ((const float4*)x)[i];
        split4h(v, g_xhi + i * 4, g_xlo + i * 4);
    } else if (bid < XBLKS + 5 * WBLKS) {
        const int wsel = (bid - XBLKS) >> 10;
        const size_t i = (size_t)((bid - XBLKS) & 1023) * 256 + t;
        const float* src; __half *hi, *lo;
        switch (wsel) {
            case 0:  src = W_in;  hi = g_Winh; lo = g_Winl; break;
            case 1:  src = Bm;    hi = g_Bh;   lo = g_Bl;   break;
            case 2:  src = W_g;   hi = g_Wgh;  lo = g_Wgl;  break;
            case 3:  src = Am;    hi = g_Ah;   lo = g_Al;   break;
            default: src = W_out; hi = g_Woh;  lo = g_Wol;  break;
        }
        float4 v = ((const float4*)src)[i];
        split4h(v, hi + i * 4, lo + i * 4);
    } else {
        const int i = (bid - XBLKS - 5 * WBLKS) * 256 + t;
        if (i < 128 * 32) g_flags[i] = 0u;
    }
}

// ---------------- wmma GEMM (round-10 proven: 256 thr, 64x32 warp tile) ----
#define MODE_PLAIN  0
#define MODE_PSPLIT 1
#define MODE_SIGW   2
#define MODE_ADDC   3
#define MODE_OUTP   4

#define SLD      24
#define MAT_B    (128 * SLD * 2)
#define STAGE_B  (4 * MAT_B)
#define CS_LD    132
#define GSM      (128 * CS_LD * 4)

template <int MODE>
__global__ void __launch_bounds__(256, 1)
gemm_wm(const __half* __restrict__ Xhi, const __half* __restrict__ Xlo,
        const __half* __restrict__ Whi, const __half* __restrict__ Wlo,
        const float* __restrict__ bias, const float* __restrict__ aux,
        float* __restrict__ C, __half* __restrict__ Chi, __half* __restrict__ Clo)
{
    extern __shared__ char dyn[];

    const int tid  = threadIdx.x;
    const int wid  = tid >> 5;
    const int row0 = blockIdx.y * 128;
    const int col0 = blockIdx.x * 128;

    const int r = tid >> 1;
    const int h = tid & 1;
    const __half* gp[4] = {
        Xhi + (size_t)(row0 + r) * DIMN + h * 8,
        Xlo + (size_t)(row0 + r) * DIMN + h * 8,
        Whi + (size_t)(col0 + r) * DIMN + h * 8,
        Wlo + (size_t)(col0 + r) * DIMN + h * 8 };
    uint4 rg[4];

    auto gload = [&](int kc) {
#pragma unroll
        for (int q = 0; q < 4; q++)
            rg[q] = *(const uint4*)(gp[q] + kc * 16);
    };
    auto sstore = [&](int st) {
        char* sb = dyn + st * STAGE_B + r * (SLD * 2) + h * 16;
#pragma unroll
        for (int q = 0; q < 4; q++)
            *(uint4*)(sb + q * MAT_B) = rg[q];
    };

    const int wm = wid & 1;
    const int wn = wid >> 1;
    wmma::fragment<wmma::accumulator, 16, 16, 16, float> acc[4][2];
#pragma unroll
    for (int mi = 0; mi < 4; mi++)
#pragma unroll
        for (int ni = 0; ni < 2; ni++) wmma::fill_fragment(acc[mi][ni], 0.0f);

    gload(0);
    sstore(0);

    for (int kc = 0; kc < 64; kc++) {
        const int cur = kc & 1;
        __syncthreads();
        if (kc < 63) gload(kc + 1);

        const __half* sA_h = (const __half*)(dyn + cur * STAGE_B);
        const __half* sA_l = (const __half*)(dyn + cur * STAGE_B + MAT_B);
        const __half* sB_h = (const __half*)(dyn + cur * STAGE_B + 2 * MAT_B);
        const __half* sB_l = (const __half*)(dyn + cur * STAGE_B + 3 * MAT_B);

        wmma::fragment<wmma::matrix_a, 16, 16, 16, __half, wmma::row_major> fa_h[4], fa_l[4];
#pragma unroll
        for (int mi = 0; mi < 4; mi++) {
            wmma::load_matrix_sync(fa_h[mi], sA_h + (wm * 64 + mi * 16) * SLD, SLD);
            wmma::load_matrix_sync(fa_l[mi], sA_l + (wm * 64 + mi * 16) * SLD, SLD);
        }
#pragma unroll
        for (int ni = 0; ni < 2; ni++) {
            wmma::fragment<wmma::matrix_b, 16, 16, 16, __half, wmma::col_major> fb_h, fb_l;
            wmma::load_matrix_sync(fb_h, sB_h + (wn * 32 + ni * 16) * SLD, SLD);
            wmma::load_matrix_sync(fb_l, sB_l + (wn * 32 + ni * 16) * SLD, SLD);
#pragma unroll
            for (int mi = 0; mi < 4; mi++) {
                wmma::mma_sync(acc[mi][ni], fa_h[mi], fb_h, acc[mi][ni]);
                wmma::mma_sync(acc[mi][ni], fa_h[mi], fb_l, acc[mi][ni]);
                wmma::mma_sync(acc[mi][ni], fa_l[mi], fb_h, acc[mi][ni]);
            }
        }

        if (kc < 63) sstore((kc + 1) & 1);
    }
    __syncthreads();

    float* Cs = (float*)dyn;
#pragma unroll
    for (int mi = 0; mi < 4; mi++)
#pragma unroll
        for (int ni = 0; ni < 2; ni++)
            wmma::store_matrix_sync(&Cs[(wm * 64 + mi * 16) * CS_LD + wn * 32 + ni * 16],
                                    acc[mi][ni], CS_LD, wmma::mem_row_major);
    __syncthreads();

    const int tx = tid & 15;
    const int ty = tid >> 4;
#pragma unroll
    for (int mi = 0; mi < 8; mi++) {
        const int lm = ty * 8 + mi;
        const int m  = row0 + lm;
#pragma unroll
        for (int q = 0; q < 2; q++) {
            const int lc = tx * 8 + q * 4;
            const int n  = col0 + lc;
            float4 a = *(const float4*)&Cs[lm * CS_LD + lc];
            if (MODE == MODE_PLAIN) {
                *(float4*)&C[(size_t)m * DIMN + n] = a;
            } else if (MODE == MODE_PSPLIT) {
                float4 bv = *(const float4*)&bias[n];
                a.x += bv.x; a.y += bv.y; a.z += bv.z; a.w += bv.w;
                const size_t idx = (size_t)m * DIMN + n;
                *(float4*)&C[idx] = a;
                split4h(a, Chi + idx, Clo + idx);
            } else if (MODE == MODE_SIGW) {
                float4 bv = *(const float4*)&bias[n];
                float s0 = 1.0f / (1.0f + expf(-(a.x + bv.x)));
                float s1 = 1.0f / (1.0f + expf(-(a.y + bv.y)));
                float s2 = 1.0f / (1.0f + expf(-(a.z + bv.z)));
                float s3 = 1.0f / (1.0f + expf(-(a.w + bv.w)));
                const size_t idx = (size_t)m * DIMN + n;
                *(float4*)&C[idx] = make_float4(s0, s1, s2, s3);
                float4 iv = *(const float4*)&aux[idx];
                float4 wv = make_float4((1.0f - s0) * iv.x, (1.0f - s1) * iv.y,
                                        (1.0f - s2) * iv.z, (1.0f - s3) * iv.w);
                split4h(wv, Chi + idx, Clo + idx);
            } else if (MODE == MODE_ADDC) {
                const size_t idx = (size_t)m * DIMN + n;
                float4 o = *(const float4*)&C[idx];
                *(float4*)&C[idx] = make_float4(o.x + a.x, o.y + a.y,
                                                o.z + a.z, o.w + a.w);
            } else {  // MODE_OUTP
                float4 bv = *(const float4*)&bias[n];
                const int tt = m >> 3, bb = m & 7;
                *(float4*)&C[((size_t)bb * SEQ + tt) * DIMN + n] =
                    make_float4(a.x + bv.x, a.y + bv.y, a.z + bv.z, a.w + bv.w);
            }
        }
    }
}

// ---------------- persistent scan kernel -----------------------------------
// Round-12 proven structure (best: 19.47 ms) with ONE change: the
// post-phase-3 full-CTA sync is narrowed to a named barrier among the 64
// writer threads (bar.sync 1,64 -> happens-before into tid0's cumulative
// release), and the dedicated poller warps (tid>=128) start polling
// immediately after the red-sync, overlapping poll-detect latency with
// phase 3.
#define GBLK 128
#define SCAN_SMEM ((16 * 1028 + 256) * 4)

__global__ void __launch_bounds__(256, 1)
scan_kernel(const float* __restrict__ gate, const float* __restrict__ v,
            const float* __restrict__ A, float* __restrict__ blended,
            __half* __restrict__ shi, __half* __restrict__ slo)
{
    extern __shared__ float sm[];
    float* As  = sm;                 // [8][1028]
    float* bl  = sm + 8 * 1028;      // [8][1028]
    float* red = sm + 16 * 1028;     // [256]

    const int tid = threadIdx.x;
    const int g   = blockIdx.x;

    {
        const float* Ap = A + (size_t)g * 8 * DIMN;
        for (int i = tid * 4; i < 8 * DIMN; i += 256 * 4) {
            const int e = i >> 10, d = i & 1023;
            float4 val = *(const float4*)&Ap[(size_t)e * DIMN + d];
            *(float4*)&As[e * 1028 + d] = val;
        }
    }

    const int b_o = tid & 7;
    const int e_o = (tid >> 3) & 7;
    const int kq  = tid >> 6;
    const int eg  = g * 8 + e_o;
    const int rot = (g * 8) & 1023;
    const int off = (tid * 4 + rot) & 1023;

    unsigned* myflag   = &g_flags[g * 32];
    unsigned* pollflag = (tid >= 128) ? &g_flags[(tid - 128) * 32] : nullptr;

    float pv  = 0.0f;
    float pgn = 0.0f;
    if (tid < 64) {
        pv  = v   [((size_t)b_o * SEQ + 0) * DIMN + eg];
        pgn = gate[((size_t)b_o * SEQ + 1) * DIMN + eg];
    }

    __syncthreads();

    for (int t = 0; t < SEQ; t++) {
        // ---- phase 1: stage blended_t into smem (t=0: zeros)
        if (t == 0) {
#pragma unroll
            for (int j = 0; j < 8; j++)
                *(float4*)&bl[j * 1028 + off] = make_float4(0.f, 0.f, 0.f, 0.f);
        } else {
            const float* src = blended + (size_t)(t & 1) * (BATCH * DIMN);
#pragma unroll
            for (int j = 0; j < 8; j++) {
                float4 s4 = __ldcg((const float4*)&src[j * DIMN + off]);
                *(float4*)&bl[j * 1028 + off] = s4;
            }
        }
        __syncthreads();

        // ---- phase 2: partial dot over this thread's 256 d's
        unsigned long long a0 = 0ull, a1 = 0ull;
        const float* ap = &As[e_o * 1028 + kq * 256];
        const float* xp = &bl[b_o * 1028 + kq * 256];
#pragma unroll 8
        for (int j = 0; j < 64; j++) {
            ulonglong2 av = *(const ulonglong2*)(ap + j * 4);
            ulonglong2 xv = *(const ulonglong2*)(xp + j * 4);
            a0 = fma2(av.x, xv.x, a0);
            a1 = fma2(av.y, xv.y, a1);
        }
        red[tid] = lo32(a0) + hi32(a0) + lo32(a1) + hi32(a1);
        __syncthreads();                        // red[] complete

        if (t + 1 < SEQ) {
            if (tid < 64) {
                // ---- phase 3: combine, tanh, publish blended
                float tot = red[tid] + red[tid + 64] + red[tid + 128] + red[tid + 192];
                float val = tanhf(tot + pv);
                blended[(size_t)((t + 1) & 1) * (BATCH * DIMN) + b_o * DIMN + eg]
                    = pgn * val;

                // writers-only barrier: blended stores happen-before release
                asm volatile("bar.sync 1, 64;" ::: "memory");
                if (tid == 0) st_release_u32(myflag, (unsigned)(t + 1));

                // deferred: state stores + next-step prefetch (poll window)
                const size_t sidx = ((size_t)t * BATCH + b_o) * DIMN + eg;
                __half hv = __float2half_rn(val);
                shi[sidx] = hv;
                slo[sidx] = __float2half_rn(val - __half2float(hv));
                pv  = v[((size_t)b_o * SEQ + (t + 1)) * DIMN + eg];
                pgn = (t + 2 < SEQ)
                    ? gate[((size_t)b_o * SEQ + (t + 2)) * DIMN + eg] : 0.0f;
            } else if (tid >= 128) {
                // dedicated pollers: start immediately (overlap with phase 3)
                const unsigned tgt = (unsigned)(t + 1);
                while (ld_acquire_u32(pollflag) < tgt) {}
            }
            __syncthreads();                    // rejoin: flag seen by pollers
        } else {
            if (tid < 64) {
                float tot = red[tid] + red[tid + 64] + red[tid + 128] + red[tid + 192];
                float val = tanhf(tot + pv);
                const size_t sidx = ((size_t)t * BATCH + b_o) * DIMN + eg;
                __half hv = __float2half_rn(val);
                shi[sidx] = hv;
                slo[sidx] = __float2half_rn(val - __half2float(hv));
            }
        }
    }
}

// ---------------- host launcher --------------------------------------------
extern "C" void kernel_launch(void* const* d_in, const int* in_sizes, int n_in,
                              void* d_out, int out_size)
{
    (void)in_sizes; (void)n_in; (void)out_size;

    const float* x     = (const float*)d_in[0];
    const float* A     = (const float*)d_in[1];
    const float* B     = (const float*)d_in[2];
    const float* W_in  = (const float*)d_in[3];
    const float* b_in  = (const float*)d_in[4];
    const float* W_g   = (const float*)d_in[5];
    const float* b_g   = (const float*)d_in[6];
    const float* W_out = (const float*)d_in[7];
    const float* b_out = (const float*)d_in[8];
    float* out = (float*)d_out;

    float *inp, *gate, *u, *blended;
    cudaGetSymbolAddress((void**)&inp,     g_inp);
    cudaGetSymbolAddress((void**)&gate,    g_gate);
    cudaGetSymbolAddress((void**)&u,       g_u);
    cudaGetSymbolAddress((void**)&blended, g_bl);

    __half *xhi,*xlo,*ihi,*ilo,*whi,*wlo,*shi,*slo;
    __half *Winh,*Winl,*Bh,*Bl,*Wgh,*Wgl,*Ah,*Al,*Woh,*Wol;
    cudaGetSymbolAddress((void**)&xhi, g_xhi);  cudaGetSymbolAddress((void**)&xlo, g_xlo);
    cudaGetSymbolAddress((void**)&ihi, g_ihi);  cudaGetSymbolAddress((void**)&ilo, g_ilo);
    cudaGetSymbolAddress((void**)&whi, g_whi);  cudaGetSymbolAddress((void**)&wlo, g_wlo);
    cudaGetSymbolAddress((void**)&shi, g_shi);  cudaGetSymbolAddress((void**)&slo, g_slo);
    cudaGetSymbolAddress((void**)&Winh, g_Winh); cudaGetSymbolAddress((void**)&Winl, g_Winl);
    cudaGetSymbolAddress((void**)&Bh,   g_Bh);   cudaGetSymbolAddress((void**)&Bl,   g_Bl);
    cudaGetSymbolAddress((void**)&Wgh,  g_Wgh);  cudaGetSymbolAddress((void**)&Wgl,  g_Wgl);
    cudaGetSymbolAddress((void**)&Ah,   g_Ah);   cudaGetSymbolAddress((void**)&Al,   g_Al);
    cudaGetSymbolAddress((void**)&Woh,  g_Woh);  cudaGetSymbolAddress((void**)&Wol,  g_Wol);

    cudaFuncSetAttribute(scan_kernel, cudaFuncAttributeMaxDynamicSharedMemorySize, SCAN_SMEM);
    cudaFuncSetAttribute(gemm_wm<MODE_PLAIN>,  cudaFuncAttributeMaxDynamicSharedMemorySize, GSM);
    cudaFuncSetAttribute(gemm_wm<MODE_PSPLIT>, cudaFuncAttributeMaxDynamicSharedMemorySize, GSM);
    cudaFuncSetAttribute(gemm_wm<MODE_SIGW>,   cudaFuncAttributeMaxDynamicSharedMemorySize, GSM);
    cudaFuncSetAttribute(gemm_wm<MODE_ADDC>,   cudaFuncAttributeMaxDynamicSharedMemorySize, GSM);
    cudaFuncSetAttribute(gemm_wm<MODE_OUTP>,   cudaFuncAttributeMaxDynamicSharedMemorySize, GSM);

    // 0) fused prep: all fp16 splits + flag reset
    prep_kernel<<<PREP_BLKS, 256>>>(x, W_in, B, W_g, A, W_out);

    dim3 grid(8, 256), blk(256);
    // 1) inp = x @ W_in^T + b_in  (+ fp16 split of inp)
    gemm_wm<MODE_PSPLIT><<<grid, blk, GSM>>>(xhi, xlo, Winh, Winl, b_in, nullptr, inp, ihi, ilo);
    // 2) u = inp @ B^T
    gemm_wm<MODE_PLAIN ><<<grid, blk, GSM>>>(ihi, ilo, Bh, Bl, nullptr, nullptr, u, nullptr, nullptr);
    // 3) gate = sigmoid(inp @ Wg^T + b_g);  w = (1-gate)*inp (fp16 split)
    gemm_wm<MODE_SIGW  ><<<grid, blk, GSM>>>(ihi, ilo, Wgh, Wgl, b_g, inp, gate, whi, wlo);
    // 4) u += w @ A^T   (now u == v)
    gemm_wm<MODE_ADDC  ><<<grid, blk, GSM>>>(whi, wlo, Ah, Al, nullptr, nullptr, u, nullptr, nullptr);
    // 5) sequential scan (launch index 5 -> ncu target)
    scan_kernel<<<GBLK, blk, SCAN_SMEM>>>(gate, u, A, blended, shi, slo);
    // 6) out = states @ W_out^T + b_out  (permuted store)
    gemm_wm<MODE_OUTP  ><<<grid, blk, GSM>>>(shi, slo, Woh, Wol, b_out, nullptr, out, nullptr, nullptr);
}

// round 17
// speedup vs baseline: 1.0869x; 1.0869x over previous
#include <cuda_runtime.h>
#include <cuda_fp16.h>
#include <mma.h>
#include <cstdint>
#include <math.h>

using namespace nvcuda;

// Problem constants
#define SEQ   4096
#define BATCH 8
#define DIMN  1024
#define TOK   (SEQ * BATCH)                 // 32768 rows

// ---------------- scratch (device globals; no allocation allowed) ----------
__device__ float g_inp [(size_t)TOK * DIMN];
__device__ float g_gate[(size_t)TOK * DIMN];
__device__ float g_u   [(size_t)TOK * DIMN];    // becomes v after ADDC GEMM
__device__ float g_bl  [2 * BATCH * DIMN];      // blended, double-buffered
__device__ unsigned g_flags[128 * 32];          // per-CTA flag, own 128B line

// fp16 hi/lo split operands
__device__ __half g_xhi[(size_t)TOK * DIMN], g_xlo[(size_t)TOK * DIMN];
__device__ __half g_ihi[(size_t)TOK * DIMN], g_ilo[(size_t)TOK * DIMN];
__device__ __half g_whi[(size_t)TOK * DIMN], g_wlo[(size_t)TOK * DIMN];
__device__ __half g_shi[(size_t)TOK * DIMN], g_slo[(size_t)TOK * DIMN];
__device__ __half g_Winh[DIMN * DIMN], g_Winl[DIMN * DIMN];
__device__ __half g_Bh  [DIMN * DIMN], g_Bl  [DIMN * DIMN];
__device__ __half g_Wgh [DIMN * DIMN], g_Wgl [DIMN * DIMN];
__device__ __half g_Ah  [DIMN * DIMN], g_Al  [DIMN * DIMN];
__device__ __half g_Woh [DIMN * DIMN], g_Wol [DIMN * DIMN];

// ---------------- f32x2 helpers --------------------------------------------
__device__ __forceinline__ unsigned long long fma2(unsigned long long a,
                                                   unsigned long long b,
                                                   unsigned long long c) {
    unsigned long long d;
    asm("fma.rn.f32x2 %0, %1, %2, %3;" : "=l"(d) : "l"(a), "l"(b), "l"(c));
    return d;
}
__device__ __forceinline__ float lo32(unsigned long long v) { return __uint_as_float((unsigned)v); }
__device__ __forceinline__ float hi32(unsigned long long v) { return __uint_as_float((unsigned)(v >> 32)); }

// ---------------- distributed-flag barrier primitives ----------------------
__device__ __forceinline__ void st_release_u32(unsigned* p, unsigned v) {
    asm volatile("st.release.gpu.global.u32 [%0], %1;" :: "l"(p), "r"(v) : "memory");
}
__device__ __forceinline__ unsigned ld_acquire_u32(const unsigned* p) {
    unsigned v;
    asm volatile("ld.acquire.gpu.global.u32 %0, [%1];" : "=r"(v) : "l"(p) : "memory");
    return v;
}

// ---------------- fp16 hi/lo split helpers ---------------------------------
__device__ __forceinline__ void split4h(float4 v, __half* hi, __half* lo) {
    __half h0 = __float2half_rn(v.x), h1 = __float2half_rn(v.y);
    __half h2 = __float2half_rn(v.z), h3 = __float2half_rn(v.w);
    __half l0 = __float2half_rn(v.x - __half2float(h0));
    __half l1 = __float2half_rn(v.y - __half2float(h1));
    __half l2 = __float2half_rn(v.z - __half2float(h2));
    __half l3 = __float2half_rn(v.w - __half2float(h3));
    ((__half2*)hi)[0] = __halves2half2(h0, h1);
    ((__half2*)hi)[1] = __halves2half2(h2, h3);
    ((__half2*)lo)[0] = __halves2half2(l0, l1);
    ((__half2*)lo)[1] = __halves2half2(l2, l3);
}

// ---------------- fused prep: all splits + flag reset in ONE launch --------
#define XBLKS  32768                    // TOK*DIMN/4/256
#define WBLKS  1024                     // DIMN*DIMN/4/256
#define PREP_BLKS (XBLKS + 5 * WBLKS + 16)

__global__ void prep_kernel(const float* __restrict__ x,
                            const float* __restrict__ W_in,
                            const float* __restrict__ Bm,
                            const float* __restrict__ W_g,
                            const float* __restrict__ Am,
                            const float* __restrict__ W_out)
{
    const int bid = blockIdx.x;
    const int t   = threadIdx.x;
    if (bid < XBLKS) {
        const size_t i = (size_t)bid * 256 + t;
        float4 v = ((const float4*)x)[i];
        split4h(v, g_xhi + i * 4, g_xlo + i * 4);
    } else if (bid < XBLKS + 5 * WBLKS) {
        const int wsel = (bid - XBLKS) >> 10;
        const size_t i = (size_t)((bid - XBLKS) & 1023) * 256 + t;
        const float* src; __half *hi, *lo;
        switch (wsel) {
            case 0:  src = W_in;  hi = g_Winh; lo = g_Winl; break;
            case 1:  src = Bm;    hi = g_Bh;   lo = g_Bl;   break;
            case 2:  src = W_g;   hi = g_Wgh;  lo = g_Wgl;  break;
            case 3:  src = Am;    hi = g_Ah;   lo = g_Al;   break;
            default: src = W_out; hi = g_Woh;  lo = g_Wol;  break;
        }
        float4 v = ((const float4*)src)[i];
        split4h(v, hi + i * 4, lo + i * 4);
    } else {
        const int i = (bid - XBLKS - 5 * WBLKS) * 256 + t;
        if (i < 128 * 32) g_flags[i] = 0u;
    }
}

// ---------------- wmma GEMM: round-10 structure, K-chunk widened to 32 -----
// fp16 2-word split, 3 products (hh, hl, lh), fp32 accumulate.
// CTA tile 128x128, K-chunk 32 (2 sub-k MMA passes per chunk), 256 threads,
// warp tile 64x32 (PROVEN — do not shrink), double-buffered smem.
// Halves barrier count (64->32) and doubles MMA span per sync so the LDG
// prefetch latency hides under compute.
#define MODE_PLAIN  0
#define MODE_PSPLIT 1
#define MODE_SIGW   2
#define MODE_ADDC   3
#define MODE_OUTP   4

#define SLD2     40                     // smem halves per row (32 + 8 pad)
#define MAT2_B   (128 * SLD2 * 2)       // 10240 B, one 128x32 fp16 matrix
#define STAGE2_B (4 * MAT2_B)           // 40960 B
#define CS_LD    132
#define GSM      (2 * STAGE2_B)         // 81920 B (> 128*132*4 = 67584)

template <int MODE>
__global__ void __launch_bounds__(256, 1)
gemm_wm(const __half* __restrict__ Xhi, const __half* __restrict__ Xlo,
        const __half* __restrict__ Whi, const __half* __restrict__ Wlo,
        const float* __restrict__ bias, const float* __restrict__ aux,
        float* __restrict__ C, __half* __restrict__ Chi, __half* __restrict__ Clo)
{
    extern __shared__ char dyn[];

    const int tid  = threadIdx.x;
    const int wid  = tid >> 5;
    const int row0 = blockIdx.y * 128;
    const int col0 = blockIdx.x * 128;

    // staging: thread -> (row r, 32B half h); 32 halves per row per chunk
    const int r = tid >> 1;
    const int h = tid & 1;
    const __half* gp[4] = {
        Xhi + (size_t)(row0 + r) * DIMN + h * 16,
        Xlo + (size_t)(row0 + r) * DIMN + h * 16,
        Whi + (size_t)(col0 + r) * DIMN + h * 16,
        Wlo + (size_t)(col0 + r) * DIMN + h * 16 };
    uint4 rg[4][2];

    auto gload = [&](int kc) {
#pragma unroll
        for (int q = 0; q < 4; q++) {
            rg[q][0] = *(const uint4*)(gp[q] + kc * 32);
            rg[q][1] = *(const uint4*)(gp[q] + kc * 32 + 8);
        }
    };
    auto sstore = [&](int st) {
        char* sb = dyn + st * STAGE2_B + r * (SLD2 * 2) + h * 32;
#pragma unroll
        for (int q = 0; q < 4; q++) {
            *(uint4*)(sb + q * MAT2_B)      = rg[q][0];
            *(uint4*)(sb + q * MAT2_B + 16) = rg[q][1];
        }
    };

    const int wm = wid & 1;              // 0..1 : 64 m-rows
    const int wn = wid >> 1;             // 0..3 : 32 n-cols
    wmma::fragment<wmma::accumulator, 16, 16, 16, float> acc[4][2];
#pragma unroll
    for (int mi = 0; mi < 4; mi++)
#pragma unroll
        for (int ni = 0; ni < 2; ni++) wmma::fill_fragment(acc[mi][ni], 0.0f);

    gload(0);
    sstore(0);

    for (int kc = 0; kc < 32; kc++) {
        const int cur = kc & 1;
        __syncthreads();                 // stage cur ready; prev readers done
        if (kc < 31) gload(kc + 1);

        const __half* sA_h = (const __half*)(dyn + cur * STAGE2_B);
        const __half* sA_l = (const __half*)(dyn + cur * STAGE2_B + MAT2_B);
        const __half* sB_h = (const __half*)(dyn + cur * STAGE2_B + 2 * MAT2_B);
        const __half* sB_l = (const __half*)(dyn + cur * STAGE2_B + 3 * MAT2_B);

#pragma unroll
        for (int s = 0; s < 2; s++) {    // two k=16 sub-steps per chunk
            const int ko = s * 16;
            wmma::fragment<wmma::matrix_a, 16, 16, 16, __half, wmma::row_major> fa_h[4], fa_l[4];
#pragma unroll
            for (int mi = 0; mi < 4; mi++) {
                wmma::load_matrix_sync(fa_h[mi], sA_h + (wm * 64 + mi * 16) * SLD2 + ko, SLD2);
                wmma::load_matrix_sync(fa_l[mi], sA_l + (wm * 64 + mi * 16) * SLD2 + ko, SLD2);
            }
#pragma unroll
            for (int ni = 0; ni < 2; ni++) {
                wmma::fragment<wmma::matrix_b, 16, 16, 16, __half, wmma::col_major> fb_h, fb_l;
                wmma::load_matrix_sync(fb_h, sB_h + (wn * 32 + ni * 16) * SLD2 + ko, SLD2);
                wmma::load_matrix_sync(fb_l, sB_l + (wn * 32 + ni * 16) * SLD2 + ko, SLD2);
#pragma unroll
                for (int mi = 0; mi < 4; mi++) {
                    wmma::mma_sync(acc[mi][ni], fa_h[mi], fb_h, acc[mi][ni]);
                    wmma::mma_sync(acc[mi][ni], fa_h[mi], fb_l, acc[mi][ni]);
                    wmma::mma_sync(acc[mi][ni], fa_l[mi], fb_h, acc[mi][ni]);
                }
            }
        }

        if (kc < 31) sstore((kc + 1) & 1);
    }
    __syncthreads();                     // all compute done; reuse smem as Cs

    float* Cs = (float*)dyn;
#pragma unroll
    for (int mi = 0; mi < 4; mi++)
#pragma unroll
        for (int ni = 0; ni < 2; ni++)
            wmma::store_matrix_sync(&Cs[(wm * 64 + mi * 16) * CS_LD + wn * 32 + ni * 16],
                                    acc[mi][ni], CS_LD, wmma::mem_row_major);
    __syncthreads();

    const int tx = tid & 15;
    const int ty = tid >> 4;
#pragma unroll
    for (int mi = 0; mi < 8; mi++) {
        const int lm = ty * 8 + mi;
        const int m  = row0 + lm;
#pragma unroll
        for (int q = 0; q < 2; q++) {
            const int lc = tx * 8 + q * 4;
            const int n  = col0 + lc;
            float4 a = *(const float4*)&Cs[lm * CS_LD + lc];
            if (MODE == MODE_PLAIN) {
                *(float4*)&C[(size_t)m * DIMN + n] = a;
            } else if (MODE == MODE_PSPLIT) {
                float4 bv = *(const float4*)&bias[n];
                a.x += bv.x; a.y += bv.y; a.z += bv.z; a.w += bv.w;
                const size_t idx = (size_t)m * DIMN + n;
                *(float4*)&C[idx] = a;
                split4h(a, Chi + idx, Clo + idx);
            } else if (MODE == MODE_SIGW) {
                float4 bv = *(const float4*)&bias[n];
                float s0 = 1.0f / (1.0f + expf(-(a.x + bv.x)));
                float s1 = 1.0f / (1.0f + expf(-(a.y + bv.y)));
                float s2 = 1.0f / (1.0f + expf(-(a.z + bv.z)));
                float s3 = 1.0f / (1.0f + expf(-(a.w + bv.w)));
                const size_t idx = (size_t)m * DIMN + n;
                *(float4*)&C[idx] = make_float4(s0, s1, s2, s3);
                float4 iv = *(const float4*)&aux[idx];
                float4 wv = make_float4((1.0f - s0) * iv.x, (1.0f - s1) * iv.y,
                                        (1.0f - s2) * iv.z, (1.0f - s3) * iv.w);
                split4h(wv, Chi + idx, Clo + idx);
            } else if (MODE == MODE_ADDC) {
                const size_t idx = (size_t)m * DIMN + n;
                float4 o = *(const float4*)&C[idx];
                *(float4*)&C[idx] = make_float4(o.x + a.x, o.y + a.y,
                                                o.z + a.z, o.w + a.w);
            } else {  // MODE_OUTP
                float4 bv = *(const float4*)&bias[n];
                const int tt = m >> 3, bb = m & 7;
                *(float4*)&C[((size_t)bb * SEQ + tt) * DIMN + n] =
                    make_float4(a.x + bv.x, a.y + bv.y, a.z + bv.z, a.w + bv.w);
            }
        }
    }
}

// ---------------- persistent scan kernel (round-13 structure, VERBATIM) ----
// Measured local optimum (19.47 ms config). Do not perturb without scan ncu.
#define GBLK 128
#define SCAN_SMEM ((16 * 1028 + 256) * 4)

__global__ void __launch_bounds__(256, 1)
scan_kernel(const float* __restrict__ gate, const float* __restrict__ v,
            const float* __restrict__ A, float* __restrict__ blended,
            __half* __restrict__ shi, __half* __restrict__ slo)
{
    extern __shared__ float sm[];
    float* As  = sm;                 // [8][1028]
    float* bl  = sm + 8 * 1028;      // [8][1028]
    float* red = sm + 16 * 1028;     // [256]

    const int tid = threadIdx.x;
    const int g   = blockIdx.x;

    {
        const float* Ap = A + (size_t)g * 8 * DIMN;
        for (int i = tid * 4; i < 8 * DIMN; i += 256 * 4) {
            const int e = i >> 10, d = i & 1023;
            float4 val = *(const float4*)&Ap[(size_t)e * DIMN + d];
            *(float4*)&As[e * 1028 + d] = val;
        }
    }

    const int b_o = tid & 7;
    const int e_o = (tid >> 3) & 7;
    const int kq  = tid >> 6;
    const int eg  = g * 8 + e_o;
    const int rot = (g * 8) & 1023;
    const int off = (tid * 4 + rot) & 1023;

    unsigned* myflag   = &g_flags[g * 32];
    unsigned* pollflag = (tid >= 128) ? &g_flags[(tid - 128) * 32] : nullptr;

    float pv  = 0.0f;
    float pgn = 0.0f;
    if (tid < 64) {
        pv  = v   [((size_t)b_o * SEQ + 0) * DIMN + eg];
        pgn = gate[((size_t)b_o * SEQ + 1) * DIMN + eg];
    }

    __syncthreads();

    for (int t = 0; t < SEQ; t++) {
        // ---- phase 1: stage blended_t into smem (t=0: zeros)
        if (t == 0) {
#pragma unroll
            for (int j = 0; j < 8; j++)
                *(float4*)&bl[j * 1028 + off] = make_float4(0.f, 0.f, 0.f, 0.f);
        } else {
            const float* src = blended + (size_t)(t & 1) * (BATCH * DIMN);
#pragma unroll
            for (int j = 0; j < 8; j++) {
                float4 s4 = __ldcg((const float4*)&src[j * DIMN + off]);
                *(float4*)&bl[j * 1028 + off] = s4;
            }
        }
        __syncthreads();

        // ---- phase 2: partial dot over this thread's 256 d's
        unsigned long long a0 = 0ull, a1 = 0ull;
        const float* ap = &As[e_o * 1028 + kq * 256];
        const float* xp = &bl[b_o * 1028 + kq * 256];
#pragma unroll 8
        for (int j = 0; j < 64; j++) {
            ulonglong2 av = *(const ulonglong2*)(ap + j * 4);
            ulonglong2 xv = *(const ulonglong2*)(xp + j * 4);
            a0 = fma2(av.x, xv.x, a0);
            a1 = fma2(av.y, xv.y, a1);
        }
        red[tid] = lo32(a0) + hi32(a0) + lo32(a1) + hi32(a1);
        __syncthreads();

        // ---- phase 3: combine, tanh, publish ONLY blended (release-critical)
        float val = 0.0f;
        if (tid < 64) {
            float tot = red[tid] + red[tid + 64] + red[tid + 128] + red[tid + 192];
            val = tanhf(tot + pv);
            if (t + 1 < SEQ)
                blended[(size_t)((t + 1) & 1) * (BATCH * DIMN) + b_o * DIMN + eg]
                    = pgn * val;
        }

        if (t + 1 < SEQ) {
            __syncthreads();   // blended stores issued (CTA fence cumulativity)

            if (tid == 0) st_release_u32(myflag, (unsigned)(t + 1));

            // ---- deferred work in the poll window: state stores + prefetch
            if (tid < 64) {
                const size_t sidx = ((size_t)t * BATCH + b_o) * DIMN + eg;
                __half hv = __float2half_rn(val);
                shi[sidx] = hv;
                slo[sidx] = __float2half_rn(val - __half2float(hv));
                pv  = v[((size_t)b_o * SEQ + (t + 1)) * DIMN + eg];
                pgn = (t + 2 < SEQ)
                    ? gate[((size_t)b_o * SEQ + (t + 2)) * DIMN + eg] : 0.0f;
            }

            if (tid >= 128) {
                const unsigned tgt = (unsigned)(t + 1);
                while (ld_acquire_u32(pollflag) < tgt) {}
            }
            __syncthreads();
        } else {
            if (tid < 64) {
                const size_t sidx = ((size_t)t * BATCH + b_o) * DIMN + eg;
                __half hv = __float2half_rn(val);
                shi[sidx] = hv;
                slo[sidx] = __float2half_rn(val - __half2float(hv));
            }
        }
    }
}

// ---------------- host launcher --------------------------------------------
extern "C" void kernel_launch(void* const* d_in, const int* in_sizes, int n_in,
                              void* d_out, int out_size)
{
    (void)in_sizes; (void)n_in; (void)out_size;

    const float* x     = (const float*)d_in[0];
    const float* A     = (const float*)d_in[1];
    const float* B     = (const float*)d_in[2];
    const float* W_in  = (const float*)d_in[3];
    const float* b_in  = (const float*)d_in[4];
    const float* W_g   = (const float*)d_in[5];
    const float* b_g   = (const float*)d_in[6];
    const float* W_out = (const float*)d_in[7];
    const float* b_out = (const float*)d_in[8];
    float* out = (float*)d_out;

    float *inp, *gate, *u, *blended;
    cudaGetSymbolAddress((void**)&inp,     g_inp);
    cudaGetSymbolAddress((void**)&gate,    g_gate);
    cudaGetSymbolAddress((void**)&u,       g_u);
    cudaGetSymbolAddress((void**)&blended, g_bl);

    __half *xhi,*xlo,*ihi,*ilo,*whi,*wlo,*shi,*slo;
    __half *Winh,*Winl,*Bh,*Bl,*Wgh,*Wgl,*Ah,*Al,*Woh,*Wol;
    cudaGetSymbolAddress((void**)&xhi, g_xhi);  cudaGetSymbolAddress((void**)&xlo, g_xlo);
    cudaGetSymbolAddress((void**)&ihi, g_ihi);  cudaGetSymbolAddress((void**)&ilo, g_ilo);
    cudaGetSymbolAddress((void**)&whi, g_whi);  cudaGetSymbolAddress((void**)&wlo, g_wlo);
    cudaGetSymbolAddress((void**)&shi, g_shi);  cudaGetSymbolAddress((void**)&slo, g_slo);
    cudaGetSymbolAddress((void**)&Winh, g_Winh); cudaGetSymbolAddress((void**)&Winl, g_Winl);
    cudaGetSymbolAddress((void**)&Bh,   g_Bh);   cudaGetSymbolAddress((void**)&Bl,   g_Bl);
    cudaGetSymbolAddress((void**)&Wgh,  g_Wgh);  cudaGetSymbolAddress((void**)&Wgl,  g_Wgl);
    cudaGetSymbolAddress((void**)&Ah,   g_Ah);   cudaGetSymbolAddress((void**)&Al,   g_Al);
    cudaGetSymbolAddress((void**)&Woh,  g_Woh);  cudaGetSymbolAddress((void**)&Wol,  g_Wol);

    cudaFuncSetAttribute(scan_kernel, cudaFuncAttributeMaxDynamicSharedMemorySize, SCAN_SMEM);
    cudaFuncSetAttribute(gemm_wm<MODE_PLAIN>,  cudaFuncAttributeMaxDynamicSharedMemorySize, GSM);
    cudaFuncSetAttribute(gemm_wm<MODE_PSPLIT>, cudaFuncAttributeMaxDynamicSharedMemorySize, GSM);
    cudaFuncSetAttribute(gemm_wm<MODE_SIGW>,   cudaFuncAttributeMaxDynamicSharedMemorySize, GSM);
    cudaFuncSetAttribute(gemm_wm<MODE_ADDC>,   cudaFuncAttributeMaxDynamicSharedMemorySize, GSM);
    cudaFuncSetAttribute(gemm_wm<MODE_OUTP>,   cudaFuncAttributeMaxDynamicSharedMemorySize, GSM);

    // 0) fused prep: all fp16 splits + flag reset
    prep_kernel<<<PREP_BLKS, 256>>>(x, W_in, B, W_g, A, W_out);

    dim3 grid(8, 256), blk(256);
    // 1) inp = x @ W_in^T + b_in  (+ fp16 split of inp)
    gemm_wm<MODE_PSPLIT><<<grid, blk, GSM>>>(xhi, xlo, Winh, Winl, b_in, nullptr, inp, ihi, ilo);
    // 2) u = inp @ B^T
    gemm_wm<MODE_PLAIN ><<<grid, blk, GSM>>>(ihi, ilo, Bh, Bl, nullptr, nullptr, u, nullptr, nullptr);
    // 3) gate = sigmoid(inp @ Wg^T + b_g);  w = (1-gate)*inp (fp16 split)
    gemm_wm<MODE_SIGW  ><<<grid, blk, GSM>>>(ihi, ilo, Wgh, Wgl, b_g, inp, gate, whi, wlo);
    // 4) u += w @ A^T   (now u == v)
    gemm_wm<MODE_ADDC  ><<<grid, blk, GSM>>>(whi, wlo, Ah, Al, nullptr, nullptr, u, nullptr, nullptr);
    // 5) sequential scan (round-13 verbatim; launch index 5 -> ncu target)
    scan_kernel<<<GBLK, blk, SCAN_SMEM>>>(gate, u, A, blended, shi, slo);
    // 6) out = states @ W_out^T + b_out  (permuted store)
    gemm_wm<MODE_OUTP  ><<<grid, blk, GSM>>>(shi, slo, Woh, Wol, b_out, nullptr, out, nullptr, nullptr);
}